// round 4
// baseline (speedup 1.0000x reference)
#include <cuda_runtime.h>

#define NN 131072
#define EE 1048576
#define GG 4096
#define SS 64
#define HH 128
#define CAP 128
#define NEG 0.2f
#define GPB 16   // graphs per block in compute kernel

// scratch (no allocs allowed) — per-(branch, graph) edge buckets
__device__ int d_cnt[2][GG];
__device__ int d_srcbuf[2][GG * CAP];
__device__ int d_is32;   // 1 if edge_index is int32, 0 if int64

__global__ void detect_dtype_kernel(const int* __restrict__ up_e_words) {
    // If the buffer is int64, every odd 32-bit word is the high word of a
    // non-negative value < 2^31 -> 0. If int32, odd words are node ids.
    if (blockIdx.x == 0 && threadIdx.x == 0) {
        int any = 0;
        #pragma unroll
        for (int i = 0; i < 64; i++) any |= up_e_words[2 * i + 1];
        d_is32 = (any != 0) ? 1 : 0;
    }
}

__global__ void zero_cnt_kernel() {
    int i = blockIdx.x * blockDim.x + threadIdx.x;
    if (i < 2 * GG) ((int*)d_cnt)[i] = 0;
}

__global__ void filter_edges_kernel(const void* __restrict__ up_e,
                                    const void* __restrict__ down_e) {
    long long i = (long long)blockIdx.x * blockDim.x + threadIdx.x;
    int b = 0;
    const void* ep = up_e;
    if (i >= EE) { b = 1; ep = down_e; i -= EE; }

    int dst;
    if (d_is32) dst = ((const int*)ep)[EE + i];
    else        dst = (int)((const long long*)ep)[EE + i];

    if ((dst & 31) == 31) {              // only edges into the self node matter
        int g = dst >> 5;
        int src;
        if (d_is32) src = ((const int*)ep)[i];
        else        src = (int)((const long long*)ep)[i];
        int pos = atomicAdd(&d_cnt[b][g], 1);
        if (pos < CAP) d_srcbuf[b][g * CAP + pos] = src;
    }
}

// shared layout (floats):
//   shW   [2][64*128]  = 16384
//   shAs  [2][128]     = 256
//   shAd  [2][128]     = 256
//   shB   [2][128]     = 256
//   shRes [2*GPB][128] = 4096
#define SH_FLOATS (16384 + 256 + 256 + 256 + 2 * GPB * HH)
#define SH_BYTES  (SH_FLOATS * 4)

extern __shared__ float sm_f[];

__global__ __launch_bounds__(256, 1)
void gat_fused_kernel(const float* __restrict__ up_x, const float* __restrict__ down_x,
                      const float* __restrict__ up_W, const float* __restrict__ up_as,
                      const float* __restrict__ up_ad, const float* __restrict__ up_b,
                      const float* __restrict__ down_W, const float* __restrict__ down_as,
                      const float* __restrict__ down_ad, const float* __restrict__ down_b,
                      const float* __restrict__ mlp_W, const float* __restrict__ mlp_b,
                      float* __restrict__ out) {
    float* shW   = sm_f;                 // [2][8192]
    float* shAs  = sm_f + 16384;         // [2][128]
    float* shAd  = sm_f + 16640;         // [2][128]
    float* shB   = sm_f + 16896;         // [2][128]
    float* shRes = sm_f + 17152;         // [2*GPB][128]

    const int tid = threadIdx.x;

    // cooperative stage of W (both branches) into shared
    {
        const float4* wu = (const float4*)up_W;
        const float4* wd = (const float4*)down_W;
        float4* s4 = (float4*)shW;
        #pragma unroll
        for (int i = tid; i < 2048; i += 256) s4[i] = wu[i];
        #pragma unroll
        for (int i = tid; i < 2048; i += 256) s4[2048 + i] = wd[i];
    }
    if (tid < HH) {
        shAs[tid]      = up_as[tid];   shAs[HH + tid] = down_as[tid];
        shAd[tid]      = up_ad[tid];   shAd[HH + tid] = down_ad[tid];
        shB[tid]       = up_b[tid];    shB[HH + tid]  = down_b[tid];
    }
    __syncthreads();

    const int w    = tid >> 5;
    const int lane = tid & 31;
    const unsigned FULL = 0xffffffffu;

    // each warp processes 4 tasks; task = gl*2 + b, gl in [0,GPB), b in {0,1}
    for (int q = 0; q < 4; q++) {
        const int task = w + 8 * q;          // 0..31
        const int b    = task & 1;
        const int gl   = task >> 1;
        const int g    = blockIdx.x * GPB + gl;

        const float* xp = b ? down_x : up_x;
        const float* Wb = shW + b * (SS * HH);
        const float* As = shAs + b * HH;
        const float* Ad = shAd + b * HH;

        // ---- matvec helper: h[4*lane..4*lane+3] of x[src] @ W ----
        #define MATVEC(src, H0, H1, H2, H3)                                          \
        {                                                                            \
            float2 xr = *(const float2*)(xp + (long long)(src) * SS + 2 * lane);     \
            H0 = H1 = H2 = H3 = 0.f;                                                 \
            _Pragma("unroll")                                                        \
            for (int k2 = 0; k2 < 32; k2++) {                                        \
                float xa = __shfl_sync(FULL, xr.x, k2);                              \
                float xb = __shfl_sync(FULL, xr.y, k2);                              \
                float4 wA = *(const float4*)(Wb + (2 * k2) * HH + 4 * lane);         \
                float4 wB = *(const float4*)(Wb + (2 * k2 + 1) * HH + 4 * lane);     \
                H0 += xa * wA.x + xb * wB.x;                                         \
                H1 += xa * wA.y + xb * wB.y;                                         \
                H2 += xa * wA.z + xb * wB.z;                                         \
                H3 += xa * wA.w + xb * wB.w;                                         \
            }                                                                        \
        }

        // self node h + a_dst
        const int self = g * 32 + 31;
        float a_dst;
        {
            float s0, s1, s2, s3;
            MATVEC(self, s0, s1, s2, s3);
            float p = s0 * Ad[4 * lane] + s1 * Ad[4 * lane + 1] +
                      s2 * Ad[4 * lane + 2] + s3 * Ad[4 * lane + 3];
            #pragma unroll
            for (int o = 16; o; o >>= 1) p += __shfl_xor_sync(FULL, p, o);
            a_dst = p;
        }

        int cnt = d_cnt[b][g];
        if (cnt > CAP) cnt = CAP;
        const int* srcs = &d_srcbuf[b][g * CAP];

        // online softmax + weighted aggregation
        float m = -1e30f, ssum = 0.f;
        float a0 = 0.f, a1 = 0.f, a2 = 0.f, a3 = 0.f;
        for (int t = 0; t < cnt; t++) {
            int src = srcs[t];
            float h0, h1, h2, h3;
            MATVEC(src, h0, h1, h2, h3);
            float p = h0 * As[4 * lane] + h1 * As[4 * lane + 1] +
                      h2 * As[4 * lane + 2] + h3 * As[4 * lane + 3];
            #pragma unroll
            for (int o = 16; o; o >>= 1) p += __shfl_xor_sync(FULL, p, o);
            float e = p + a_dst;
            e = (e > 0.f) ? e : NEG * e;               // leaky_relu
            float mn = fmaxf(m, e);
            float sc = __expf(m - mn);
            float pw = __expf(e - mn);
            ssum = ssum * sc + pw;
            a0 = a0 * sc + pw * h0;
            a1 = a1 * sc + pw * h1;
            a2 = a2 * sc + pw * h2;
            a3 = a3 * sc + pw * h3;
            m = mn;
        }

        float inv = 1.f / (ssum + 1e-16f);
        float* res = shRes + task * HH + 4 * lane;
        const float* Bb = shB + b * HH + 4 * lane;
        float o0 = a0 * inv + Bb[0];
        float o1 = a1 * inv + Bb[1];
        float o2 = a2 * inv + Bb[2];
        float o3 = a3 * inv + Bb[3];
        res[0] = 1.f / (1.f + __expf(-o0));
        res[1] = 1.f / (1.f + __expf(-o1));
        res[2] = 1.f / (1.f + __expf(-o2));
        res[3] = 1.f / (1.f + __expf(-o3));
        #undef MATVEC
    }
    __syncthreads();

    // final: up * down, dot with mlp_W, add mlp_b  (2 graphs per warp)
    const float mb = mlp_b[0];
    for (int r = 0; r < 2; r++) {
        int gl = w + 8 * r;
        const float* u = shRes + (2 * gl) * HH;
        const float* d = shRes + (2 * gl + 1) * HH;
        float p = 0.f;
        #pragma unroll
        for (int i = 0; i < 4; i++) {
            int j = 4 * lane + i;
            p += u[j] * d[j] * mlp_W[j];
        }
        #pragma unroll
        for (int o = 16; o; o >>= 1) p += __shfl_xor_sync(FULL, p, o);
        if (lane == 0) out[blockIdx.x * GPB + gl] = p + mb;
    }
}

extern "C" void kernel_launch(void* const* d_in, const int* in_sizes, int n_in,
                              void* d_out, int out_size) {
    const float* up_x    = (const float*)d_in[0];
    const void*  up_e    = d_in[1];
    const float* down_x  = (const float*)d_in[3];
    const void*  down_e  = d_in[4];
    const float* up_W    = (const float*)d_in[6];
    const float* up_as   = (const float*)d_in[7];
    const float* up_ad   = (const float*)d_in[8];
    const float* up_b    = (const float*)d_in[9];
    const float* down_W  = (const float*)d_in[10];
    const float* down_as = (const float*)d_in[11];
    const float* down_ad = (const float*)d_in[12];
    const float* down_b  = (const float*)d_in[13];
    const float* mlp_W   = (const float*)d_in[14];
    const float* mlp_b   = (const float*)d_in[15];
    float* out = (float*)d_out;

    cudaFuncSetAttribute(gat_fused_kernel,
                         cudaFuncAttributeMaxDynamicSharedMemorySize, SH_BYTES);

    detect_dtype_kernel<<<1, 32>>>((const int*)up_e);
    zero_cnt_kernel<<<(2 * GG + 255) / 256, 256>>>();
    filter_edges_kernel<<<(2 * EE) / 256, 256>>>(up_e, down_e);
    gat_fused_kernel<<<GG / GPB, 256, SH_BYTES>>>(
        up_x, down_x,
        up_W, up_as, up_ad, up_b,
        down_W, down_as, down_ad, down_b,
        mlp_W, mlp_b, out);
}

// round 5
// speedup vs baseline: 1.4154x; 1.4154x over previous
#include <cuda_runtime.h>

#define NN 131072
#define EE 1048576
#define GG 4096
#define SS 64
#define HH 128
#define CAP 128
#define NEG 0.2f
#define GPB 16   // graphs per block in compute kernel

// scratch (no allocs allowed)
__device__ int   d_cnt[2][GG];
__device__ int   d_srcbuf[2][GG * CAP];
__device__ int   d_is32;                 // 1 if edge_index is int32, 0 if int64
__device__ float d_res[2][GG][HH];       // sigmoid(branch output), 4 MB

__global__ void detect_dtype_kernel(const int* __restrict__ up_e_words) {
    // int64 buffer: odd 32-bit words are zero high-words. int32: random ids.
    if (blockIdx.x == 0 && threadIdx.x == 0) {
        int any = 0;
        #pragma unroll
        for (int i = 0; i < 64; i++) any |= up_e_words[2 * i + 1];
        d_is32 = (any != 0) ? 1 : 0;
    }
}

__global__ void zero_cnt_kernel() {
    int i = blockIdx.x * blockDim.x + threadIdx.x;
    if (i < 2 * GG) ((int*)d_cnt)[i] = 0;
}

__global__ void filter_edges_kernel(const void* __restrict__ up_e,
                                    const void* __restrict__ down_e) {
    long long i = (long long)blockIdx.x * blockDim.x + threadIdx.x;
    int b = 0;
    const void* ep = up_e;
    if (i >= EE) { b = 1; ep = down_e; i -= EE; }

    int dst;
    if (d_is32) dst = ((const int*)ep)[EE + i];
    else        dst = (int)((const long long*)ep)[EE + i];

    if ((dst & 31) == 31) {              // only edges into the self node matter
        int g = dst >> 5;
        int src;
        if (d_is32) src = ((const int*)ep)[i];
        else        src = (int)((const long long*)ep)[i];
        int pos = atomicAdd(&d_cnt[b][g], 1);
        if (pos < CAP) d_srcbuf[b][g * CAP + pos] = src;
    }
}

// ---------------- GAT branch kernel ----------------
// blockIdx.x: bit0 = branch, rest = graph-group of GPB graphs.
// 8 warps/block, each warp handles GPB/8 graphs sequentially.
__global__ __launch_bounds__(256, 2)
void gat_kernel(const float* __restrict__ up_x, const float* __restrict__ down_x,
                const float* __restrict__ up_W, const float* __restrict__ up_as,
                const float* __restrict__ up_ad, const float* __restrict__ up_b,
                const float* __restrict__ down_W, const float* __restrict__ down_as,
                const float* __restrict__ down_ad, const float* __restrict__ down_b) {
    __shared__ float shW[SS * HH];       // 32 KB
    __shared__ float shAs[HH], shAd[HH], shB[HH];

    const int tid  = threadIdx.x;
    const int b    = blockIdx.x & 1;
    const int gbase = (blockIdx.x >> 1) * GPB;

    const float* xp  = b ? down_x  : up_x;
    const float* Wp  = b ? down_W  : up_W;
    const float* asp = b ? down_as : up_as;
    const float* adp = b ? down_ad : up_ad;
    const float* bp  = b ? down_b  : up_b;

    {
        const float4* w4 = (const float4*)Wp;
        float4* s4 = (float4*)shW;
        #pragma unroll
        for (int i = tid; i < SS * HH / 4; i += 256) s4[i] = w4[i];
    }
    if (tid < HH) { shAs[tid] = asp[tid]; shAd[tid] = adp[tid]; shB[tid] = bp[tid]; }
    __syncthreads();

    const int w    = tid >> 5;
    const int lane = tid & 31;
    const unsigned FULL = 0xffffffffu;
    const int l4 = 4 * lane;

    // two h-rows per pass, sharing the W shared-memory loads
    #define MATVEC2(srcA, srcB, A0, A1, A2, A3, B0, B1, B2, B3)                  \
    {                                                                            \
        float2 xA = *(const float2*)(xp + (size_t)(srcA) * SS + 2 * lane);       \
        float2 xB = *(const float2*)(xp + (size_t)(srcB) * SS + 2 * lane);       \
        A0 = A1 = A2 = A3 = B0 = B1 = B2 = B3 = 0.f;                             \
        _Pragma("unroll 8")                                                      \
        for (int k2 = 0; k2 < 32; k2++) {                                        \
            float a0 = __shfl_sync(FULL, xA.x, k2);                              \
            float a1 = __shfl_sync(FULL, xA.y, k2);                              \
            float c0 = __shfl_sync(FULL, xB.x, k2);                              \
            float c1 = __shfl_sync(FULL, xB.y, k2);                              \
            float4 wA = *(const float4*)(shW + (2 * k2) * HH + l4);              \
            float4 wB = *(const float4*)(shW + (2 * k2 + 1) * HH + l4);          \
            A0 += a0 * wA.x + a1 * wB.x;  A1 += a0 * wA.y + a1 * wB.y;           \
            A2 += a0 * wA.z + a1 * wB.z;  A3 += a0 * wA.w + a1 * wB.w;           \
            B0 += c0 * wA.x + c1 * wB.x;  B1 += c0 * wA.y + c1 * wB.y;           \
            B2 += c0 * wA.z + c1 * wB.z;  B3 += c0 * wA.w + c1 * wB.w;           \
        }                                                                        \
    }

    #define WREDUCE(p) { _Pragma("unroll")                                       \
        for (int o = 16; o; o >>= 1) (p) += __shfl_xor_sync(FULL, (p), o); }

    for (int r = 0; r < GPB / 8; r++) {
        const int g = gbase + w + 8 * r;
        const int self = g * 32 + 31;

        int cnt = d_cnt[b][g];
        if (cnt > CAP) cnt = CAP;
        const int* srcs = &d_srcbuf[b][g * CAP];

        float m = -1e30f, ssum = 0.f;
        float q0 = 0.f, q1 = 0.f, q2 = 0.f, q3 = 0.f;

        // pair 0: (self, first edge src)
        {
            int src0 = (cnt > 0) ? srcs[0] : self;
            float s0, s1, s2, s3, h0, h1, h2, h3;
            MATVEC2(self, src0, s0, s1, s2, s3, h0, h1, h2, h3);
            float pd = s0 * shAd[l4] + s1 * shAd[l4 + 1] +
                       s2 * shAd[l4 + 2] + s3 * shAd[l4 + 3];
            WREDUCE(pd);
            float a_dst = pd;

            float pe = h0 * shAs[l4] + h1 * shAs[l4 + 1] +
                       h2 * shAs[l4 + 2] + h3 * shAs[l4 + 3];
            WREDUCE(pe);
            float e0 = pe + a_dst;
            e0 = (e0 > 0.f) ? e0 : NEG * e0;
            if (cnt == 0) e0 = -1e30f;

            m = e0;                       // first online step
            float pw = (cnt > 0) ? 1.f : 0.f;   // exp(e0 - e0)
            ssum = pw;
            q0 = pw * h0; q1 = pw * h1; q2 = pw * h2; q3 = pw * h3;

            // remaining edges in pairs
            for (int t = 1; t < cnt; t += 2) {
                int sA = srcs[t];
                int valB = (t + 1 < cnt);
                int sB = valB ? srcs[t + 1] : sA;
                float A0, A1, A2, A3, B0, B1, B2, B3;
                MATVEC2(sA, sB, A0, A1, A2, A3, B0, B1, B2, B3);

                float pA = A0 * shAs[l4] + A1 * shAs[l4 + 1] +
                           A2 * shAs[l4 + 2] + A3 * shAs[l4 + 3];
                float pB = B0 * shAs[l4] + B1 * shAs[l4 + 1] +
                           B2 * shAs[l4 + 2] + B3 * shAs[l4 + 3];
                #pragma unroll
                for (int o = 16; o; o >>= 1) {
                    pA += __shfl_xor_sync(FULL, pA, o);
                    pB += __shfl_xor_sync(FULL, pB, o);
                }
                float eA = pA + a_dst; eA = (eA > 0.f) ? eA : NEG * eA;
                float eB = pB + a_dst; eB = (eB > 0.f) ? eB : NEG * eB;
                if (!valB) eB = -1e30f;

                float mn = fmaxf(m, fmaxf(eA, eB));
                float sc = __expf(m - mn);
                float wA2 = __expf(eA - mn);
                float wB2 = __expf(eB - mn);
                ssum = ssum * sc + wA2 + wB2;
                q0 = q0 * sc + wA2 * A0 + wB2 * B0;
                q1 = q1 * sc + wA2 * A1 + wB2 * B1;
                q2 = q2 * sc + wA2 * A2 + wB2 * B2;
                q3 = q3 * sc + wA2 * A3 + wB2 * B3;
                m = mn;
            }
        }

        float inv = 1.f / (ssum + 1e-16f);
        float o0 = q0 * inv + shB[l4];
        float o1 = q1 * inv + shB[l4 + 1];
        float o2 = q2 * inv + shB[l4 + 2];
        float o3 = q3 * inv + shB[l4 + 3];
        float4 sg;
        sg.x = 1.f / (1.f + __expf(-o0));
        sg.y = 1.f / (1.f + __expf(-o1));
        sg.z = 1.f / (1.f + __expf(-o2));
        sg.w = 1.f / (1.f + __expf(-o3));
        *(float4*)&d_res[b][g][l4] = sg;
    }
    #undef MATVEC2
    #undef WREDUCE
}

// ---------------- combine: up * down -> mlp ----------------
__global__ __launch_bounds__(256)
void combine_kernel(const float* __restrict__ mlp_W, const float* __restrict__ mlp_b,
                    float* __restrict__ out) {
    const int gt   = blockIdx.x * blockDim.x + threadIdx.x;
    const int g    = gt >> 5;
    const int lane = threadIdx.x & 31;
    if (g >= GG) return;
    const unsigned FULL = 0xffffffffu;

    float4 u  = *(const float4*)&d_res[0][g][4 * lane];
    float4 d  = *(const float4*)&d_res[1][g][4 * lane];
    float4 mw = *(const float4*)&mlp_W[4 * lane];
    float p = u.x * d.x * mw.x + u.y * d.y * mw.y +
              u.z * d.z * mw.z + u.w * d.w * mw.w;
    #pragma unroll
    for (int o = 16; o; o >>= 1) p += __shfl_xor_sync(FULL, p, o);
    if (lane == 0) out[g] = p + mlp_b[0];
}

extern "C" void kernel_launch(void* const* d_in, const int* in_sizes, int n_in,
                              void* d_out, int out_size) {
    const float* up_x    = (const float*)d_in[0];
    const void*  up_e    = d_in[1];
    const float* down_x  = (const float*)d_in[3];
    const void*  down_e  = d_in[4];
    const float* up_W    = (const float*)d_in[6];
    const float* up_as   = (const float*)d_in[7];
    const float* up_ad   = (const float*)d_in[8];
    const float* up_b    = (const float*)d_in[9];
    const float* down_W  = (const float*)d_in[10];
    const float* down_as = (const float*)d_in[11];
    const float* down_ad = (const float*)d_in[12];
    const float* down_b  = (const float*)d_in[13];
    const float* mlp_W   = (const float*)d_in[14];
    const float* mlp_b   = (const float*)d_in[15];
    float* out = (float*)d_out;

    detect_dtype_kernel<<<1, 32>>>((const int*)up_e);
    zero_cnt_kernel<<<(2 * GG + 255) / 256, 256>>>();
    filter_edges_kernel<<<(2 * EE) / 256, 256>>>(up_e, down_e);
    gat_kernel<<<2 * GG / GPB, 256>>>(up_x, down_x,
                                      up_W, up_as, up_ad, up_b,
                                      down_W, down_as, down_ad, down_b);
    combine_kernel<<<(GG * 32 + 255) / 256, 256>>>(mlp_W, mlp_b, out);
}

// round 7
// speedup vs baseline: 3.6816x; 2.6011x over previous
#include <cuda_runtime.h>

#define NN 131072
#define EE 1048576
#define GG 4096
#define SS 64
#define HH 128
#define CAP 128
#define NEG 0.2f
#define FULL 0xffffffffu

// scratch (no allocs allowed)
__device__ int    d_cnt[2][GG];
__device__ int    d_srcbuf[2][GG * CAP];
__device__ int    d_is32;                // 1 if edge_index is int32, 0 if int64
__device__ float  d_wvec[2][2][SS];      // [branch][src|dst][64] collapsed att vectors
__device__ float2 d_z[2][GG][SS / 2];    // alpha-weighted x aggregate
__device__ float  d_res[2][GG][HH];      // sigmoid(branch output)

// ---- zero counters + detect edge dtype in one launch ----
__global__ void zero_detect_kernel(const int* __restrict__ up_e_words) {
    int i = blockIdx.x * blockDim.x + threadIdx.x;
    if (i < 2 * GG) ((int*)d_cnt)[i] = 0;
    if (blockIdx.x == 0 && threadIdx.x == 0) {
        // int64 buffer: odd 32-bit words are zero high-words. int32: random ids.
        int any = 0;
        #pragma unroll
        for (int j = 0; j < 64; j++) any |= up_e_words[2 * j + 1];
        d_is32 = (any != 0) ? 1 : 0;
    }
}

// ---- filter: keep only edges whose dst is the self node (32g+31), 4 edges/thread ----
__global__ void filter_edges_kernel(const void* __restrict__ up_e,
                                    const void* __restrict__ down_e) {
    const long long Q = EE / 4;
    long long i4 = (long long)blockIdx.x * blockDim.x + threadIdx.x;
    int b = 0;
    const void* ep = up_e;
    if (i4 >= Q) { b = 1; ep = down_e; i4 -= Q; }
    const int is32 = d_is32;

    int dst[4];
    if (is32) {
        int4 dd = ((const int4*)((const int*)ep + EE))[i4];
        dst[0] = dd.x; dst[1] = dd.y; dst[2] = dd.z; dst[3] = dd.w;
    } else {
        longlong2 d0 = ((const longlong2*)((const long long*)ep + EE))[2 * i4];
        longlong2 d1 = ((const longlong2*)((const long long*)ep + EE))[2 * i4 + 1];
        dst[0] = (int)d0.x; dst[1] = (int)d0.y; dst[2] = (int)d1.x; dst[3] = (int)d1.y;
    }
    #pragma unroll
    for (int j = 0; j < 4; j++) {
        if ((dst[j] & 31) == 31) {
            long long idx = 4 * i4 + j;
            int g = dst[j] >> 5;
            int src = is32 ? ((const int*)ep)[idx]
                           : (int)((const long long*)ep)[idx];
            int pos = atomicAdd(&d_cnt[b][g], 1);
            if (pos < CAP) d_srcbuf[b][g * CAP + pos] = src;
        }
    }
}

// ---- prep: w_s = W @ att_src, w_d = W @ att_dst per branch ----
__global__ void prep_kernel(const float* __restrict__ up_W, const float* __restrict__ up_as,
                            const float* __restrict__ up_ad,
                            const float* __restrict__ down_W, const float* __restrict__ down_as,
                            const float* __restrict__ down_ad) {
    __shared__ float shW[SS * HH];
    __shared__ float shA[2 * HH];
    const int b = blockIdx.x;
    const float* Wp = b ? down_W  : up_W;
    const float* as = b ? down_as : up_as;
    const float* ad = b ? down_ad : up_ad;
    const int tid = threadIdx.x;
    for (int i = tid; i < SS * HH / 4; i += 256) ((float4*)shW)[i] = ((const float4*)Wp)[i];
    if (tid < HH) { shA[tid] = as[tid]; shA[HH + tid] = ad[tid]; }
    __syncthreads();
    if (tid < 128) {
        const int which = tid >> 6;          // 0 = src, 1 = dst
        const int s     = tid & 63;
        const int lane  = tid & 31;
        const float* av = shA + which * HH;
        float acc = 0.f;
        #pragma unroll 8
        for (int jj = 0; jj < HH; jj++) {
            int j = (jj + lane) & (HH - 1);  // skew to avoid smem bank conflicts
            acc += shW[s * HH + j] * av[j];
        }
        d_wvec[b][which][s] = acc;
    }
}

// ---- edge scores + softmax + z aggregation: one warp per (branch, graph) ----
__global__ __launch_bounds__(256)
void edge_z_kernel(const float* __restrict__ up_x, const float* __restrict__ down_x) {
    const int task = blockIdx.x * 8 + (threadIdx.x >> 5);
    const int lane = threadIdx.x & 31;
    const int b = task & 1;
    const int g = task >> 1;
    const float* xp = b ? down_x : up_x;

    const float2 ws = *(const float2*)&d_wvec[b][0][2 * lane];
    const float2 wd = *(const float2*)&d_wvec[b][1][2 * lane];

    const int self = g * 32 + 31;
    float2 xs = *(const float2*)(xp + (size_t)self * SS + 2 * lane);
    float a_dst = xs.x * wd.x + xs.y * wd.y;
    #pragma unroll
    for (int o = 16; o; o >>= 1) a_dst += __shfl_xor_sync(FULL, a_dst, o);

    int cnt = d_cnt[b][g];
    if (cnt > CAP) cnt = CAP;
    const int* srcs = &d_srcbuf[b][g * CAP];

    float m = -1e30f, ssum = 0.f, zx = 0.f, zy = 0.f;

    for (int t0 = 0; t0 < cnt; t0 += 8) {
        float2 xr[8];
        float  p[8];
        #pragma unroll
        for (int j = 0; j < 8; j++) {
            int t = t0 + j;
            int src = (t < cnt) ? srcs[t] : self;   // dummy rows get pw forced 0
            xr[j] = *(const float2*)(xp + (size_t)src * SS + 2 * lane);
            p[j] = xr[j].x * ws.x + xr[j].y * ws.y;
        }
        #pragma unroll
        for (int o = 16; o; o >>= 1) {
            #pragma unroll
            for (int j = 0; j < 8; j++) p[j] += __shfl_xor_sync(FULL, p[j], o);
        }
        float e[8], cm = -1e30f;
        #pragma unroll
        for (int j = 0; j < 8; j++) {
            float v = p[j] + a_dst;
            v = (v > 0.f) ? v : NEG * v;            // leaky_relu
            if (t0 + j >= cnt) v = -1e30f;
            e[j] = v;
            cm = fmaxf(cm, v);
        }
        float mn = fmaxf(m, cm);
        float sc = __expf(m - mn);
        ssum *= sc; zx *= sc; zy *= sc;
        #pragma unroll
        for (int j = 0; j < 8; j++) {
            float pw = __expf(e[j] - mn);
            ssum += pw;
            zx += pw * xr[j].x;
            zy += pw * xr[j].y;
        }
        m = mn;
    }

    const float inv = 1.f / (ssum + 1e-16f);
    d_z[b][g][lane] = make_float2(zx * inv, zy * inv);
}

// ---- final matvec: out = sigmoid(z @ W + bias), one warp per (branch, graph) ----
__global__ __launch_bounds__(256, 2)
void final_matvec_kernel(const float* __restrict__ up_W, const float* __restrict__ up_b,
                         const float* __restrict__ down_W, const float* __restrict__ down_b) {
    __shared__ float shW[SS * HH];
    __shared__ float shB[HH];
    const int b     = blockIdx.x & 1;
    const int gbase = (blockIdx.x >> 1) * 8;
    const float* Wp = b ? down_W : up_W;
    const float* bp = b ? down_b : up_b;
    const int tid = threadIdx.x;
    for (int i = tid; i < SS * HH / 4; i += 256) ((float4*)shW)[i] = ((const float4*)Wp)[i];
    if (tid < HH) shB[tid] = bp[tid];
    __syncthreads();

    const int w = tid >> 5, lane = tid & 31, l4 = 4 * lane;
    const int g = gbase + w;
    float2 z = d_z[b][g][lane];

    float a0 = 0.f, a1 = 0.f, a2 = 0.f, a3 = 0.f;
    #pragma unroll 8
    for (int k2 = 0; k2 < 32; k2++) {
        float z0 = __shfl_sync(FULL, z.x, k2);
        float z1 = __shfl_sync(FULL, z.y, k2);
        float4 wA = *(const float4*)(shW + (2 * k2) * HH + l4);
        float4 wB = *(const float4*)(shW + (2 * k2 + 1) * HH + l4);
        a0 += z0 * wA.x + z1 * wB.x;
        a1 += z0 * wA.y + z1 * wB.y;
        a2 += z0 * wA.z + z1 * wB.z;
        a3 += z0 * wA.w + z1 * wB.w;
    }
    float4 sg;
    sg.x = 1.f / (1.f + __expf(-(a0 + shB[l4])));
    sg.y = 1.f / (1.f + __expf(-(a1 + shB[l4 + 1])));
    sg.z = 1.f / (1.f + __expf(-(a2 + shB[l4 + 2])));
    sg.w = 1.f / (1.f + __expf(-(a3 + shB[l4 + 3])));
    *(float4*)&d_res[b][g][l4] = sg;
}

// ---- combine: up * down -> mlp ----
__global__ __launch_bounds__(256)
void combine_kernel(const float* __restrict__ mlp_W, const float* __restrict__ mlp_b,
                    float* __restrict__ out) {
    const int gt   = blockIdx.x * blockDim.x + threadIdx.x;
    const int g    = gt >> 5;
    const int lane = threadIdx.x & 31;
    if (g >= GG) return;

    float4 u  = *(const float4*)&d_res[0][g][4 * lane];
    float4 d  = *(const float4*)&d_res[1][g][4 * lane];
    float4 mw = *(const float4*)&mlp_W[4 * lane];
    float p = u.x * d.x * mw.x + u.y * d.y * mw.y +
              u.z * d.z * mw.z + u.w * d.w * mw.w;
    #pragma unroll
    for (int o = 16; o; o >>= 1) p += __shfl_xor_sync(FULL, p, o);
    if (lane == 0) out[g] = p + mlp_b[0];
}

extern "C" void kernel_launch(void* const* d_in, const int* in_sizes, int n_in,
                              void* d_out, int out_size) {
    const float* up_x    = (const float*)d_in[0];
    const void*  up_e    = d_in[1];
    const float* down_x  = (const float*)d_in[3];
    const void*  down_e  = d_in[4];
    const float* up_W    = (const float*)d_in[6];
    const float* up_as   = (const float*)d_in[7];
    const float* up_ad   = (const float*)d_in[8];
    const float* up_b    = (const float*)d_in[9];
    const float* down_W  = (const float*)d_in[10];
    const float* down_as = (const float*)d_in[11];
    const float* down_ad = (const float*)d_in[12];
    const float* down_b  = (const float*)d_in[13];
    const float* mlp_W   = (const float*)d_in[14];
    const float* mlp_b   = (const float*)d_in[15];
    float* out = (float*)d_out;

    zero_detect_kernel<<<(2 * GG + 255) / 256, 256>>>((const int*)up_e);
    filter_edges_kernel<<<2 * (EE / 4) / 256, 256>>>(up_e, down_e);
    prep_kernel<<<2, 256>>>(up_W, up_as, up_ad, down_W, down_as, down_ad);
    edge_z_kernel<<<2 * GG / 8, 256>>>(up_x, down_x);
    final_matvec_kernel<<<2 * GG / 8, 256>>>(up_W, up_b, down_W, down_b);
    combine_kernel<<<(GG * 32 + 255) / 256, 256>>>(mlp_W, mlp_b, out);
}

// round 9
// speedup vs baseline: 3.6966x; 1.0041x over previous
#include <cuda_runtime.h>

#define NN 131072
#define EE 1048576
#define GG 4096
#define SS 64
#define HH 128
#define CAP 128
#define NEG 0.2f
#define FULL 0xffffffffu
#define TGPB 8   // graphs per block in fused tail

// scratch (no allocs allowed)
__device__ int    d_cnt[2][GG];
__device__ int    d_srcbuf[2][GG * CAP];
__device__ int    d_is32;                // 1 if edge_index is int32, 0 if int64
__device__ float  d_wvec[2][2][SS];      // [branch][src|dst][64] collapsed att vectors

// ---- pre: zero counters + dtype detect + prep (w_s = W@att_src, w_d = W@att_dst) ----
__global__ void pre_kernel(const int* __restrict__ up_e_words,
                           const float* __restrict__ up_W, const float* __restrict__ up_as,
                           const float* __restrict__ up_ad,
                           const float* __restrict__ down_W, const float* __restrict__ down_as,
                           const float* __restrict__ down_ad) {
    const int bid = blockIdx.x, tid = threadIdx.x;
    if (bid < 32) {
        ((int*)d_cnt)[bid * 256 + tid] = 0;
        return;
    }
    // blocks 32, 33: prep for branch b
    __shared__ float shW[SS * HH];
    __shared__ float shA[2 * HH];
    const int b = bid - 32;
    const float* Wp = b ? down_W  : up_W;
    const float* as = b ? down_as : up_as;
    const float* ad = b ? down_ad : up_ad;
    if (b == 0 && tid == 0) {
        // int64 buffer: odd 32-bit words are zero high-words. int32: random ids.
        int any = 0;
        #pragma unroll
        for (int j = 0; j < 64; j++) any |= up_e_words[2 * j + 1];
        d_is32 = (any != 0) ? 1 : 0;
    }
    for (int i = tid; i < SS * HH / 4; i += 256) ((float4*)shW)[i] = ((const float4*)Wp)[i];
    if (tid < HH) { shA[tid] = as[tid]; shA[HH + tid] = ad[tid]; }
    __syncthreads();
    if (tid < 128) {
        const int which = tid >> 6;          // 0 = src, 1 = dst
        const int s     = tid & 63;
        const int lane  = tid & 31;
        const float* av = shA + which * HH;
        float acc = 0.f;
        #pragma unroll 8
        for (int jj = 0; jj < HH; jj++) {
            int j = (jj + lane) & (HH - 1);  // skew to avoid smem bank conflicts
            acc += shW[s * HH + j] * av[j];
        }
        d_wvec[b][which][s] = acc;
    }
}

// ---- filter: keep only edges whose dst is the self node (32g+31), 8 edges/thread ----
__global__ void filter_edges_kernel(const void* __restrict__ up_e,
                                    const void* __restrict__ down_e) {
    const long long Q = EE / 8;
    long long i8 = (long long)blockIdx.x * blockDim.x + threadIdx.x;
    int b = 0;
    const void* ep = up_e;
    if (i8 >= Q) { b = 1; ep = down_e; i8 -= Q; }
    const int is32 = d_is32;

    int dst[8];
    if (is32) {
        const int4* dp = (const int4*)((const int*)ep + EE);
        int4 d0 = dp[2 * i8], d1 = dp[2 * i8 + 1];
        dst[0] = d0.x; dst[1] = d0.y; dst[2] = d0.z; dst[3] = d0.w;
        dst[4] = d1.x; dst[5] = d1.y; dst[6] = d1.z; dst[7] = d1.w;
    } else {
        const longlong2* dp = (const longlong2*)((const long long*)ep + EE);
        #pragma unroll
        for (int q = 0; q < 4; q++) {
            longlong2 dd = dp[4 * i8 + q];
            dst[2 * q] = (int)dd.x; dst[2 * q + 1] = (int)dd.y;
        }
    }
    #pragma unroll
    for (int j = 0; j < 8; j++) {
        if ((dst[j] & 31) == 31) {
            long long idx = 8 * i8 + j;
            int g = dst[j] >> 5;
            int src = is32 ? ((const int*)ep)[idx]
                           : (int)((const long long*)ep)[idx];
            int pos = atomicAdd(&d_cnt[b][g], 1);
            if (pos < CAP) d_srcbuf[b][g * CAP + pos] = src;
        }
    }
}

// ---- fused tail: edge softmax/aggregate + matvec + sigmoid + combine + mlp ----
// block = 8 warps over TGPB=8 graphs x 2 branches (2 tasks per warp)
// smem floats: shW[2][8192] | shB[2][128] | shMlp[128] | shRes[TGPB][2][128]
#define SMF (2 * SS * HH + 2 * HH + HH + TGPB * 2 * HH)
#define SMB (SMF * 4)

extern __shared__ float smf[];

__global__ __launch_bounds__(256)
void fused_tail_kernel(const float* __restrict__ up_x, const float* __restrict__ down_x,
                       const float* __restrict__ up_W, const float* __restrict__ up_b,
                       const float* __restrict__ down_W, const float* __restrict__ down_b,
                       const float* __restrict__ mlp_W, const float* __restrict__ mlp_b,
                       float* __restrict__ out) {
    float* shW   = smf;                       // [2][8192]
    float* shB   = smf + 2 * SS * HH;         // [2][128]
    float* shMlp = shB + 2 * HH;              // [128]
    float* shRes = shMlp + HH;                // [TGPB][2][128]

    const int tid = threadIdx.x;
    const int gbase = blockIdx.x * TGPB;

    {   // stage both W matrices, biases, mlp_W
        const float4* wu = (const float4*)up_W;
        const float4* wd = (const float4*)down_W;
        float4* s4 = (float4*)shW;
        #pragma unroll
        for (int i = tid; i < SS * HH / 4; i += 256) { s4[i] = wu[i]; s4[SS * HH / 4 + i] = wd[i]; }
    }
    if (tid < HH) {
        shB[tid]      = up_b[tid];
        shB[HH + tid] = down_b[tid];
        shMlp[tid]    = mlp_W[tid];
    }
    __syncthreads();

    const int w    = tid >> 5;
    const int lane = tid & 31;
    const int b    = w & 1;
    const int l4   = 4 * lane;
    const float* xp = b ? down_x : up_x;
    const float* Wb = shW + b * (SS * HH);

    const float2 ws = *(const float2*)&d_wvec[b][0][2 * lane];
    const float2 wd = *(const float2*)&d_wvec[b][1][2 * lane];

    #pragma unroll
    for (int r = 0; r < 2; r++) {
        const int gl = (w >> 1) + 4 * r;      // 0..7
        const int g  = gbase + gl;
        const int self = g * 32 + 31;

        // a_dst
        float2 xs = *(const float2*)(xp + (size_t)self * SS + 2 * lane);
        float a_dst = xs.x * wd.x + xs.y * wd.y;
        #pragma unroll
        for (int o = 16; o; o >>= 1) a_dst += __shfl_xor_sync(FULL, a_dst, o);

        int cnt = d_cnt[b][g];
        if (cnt > CAP) cnt = CAP;
        const int* srcs = &d_srcbuf[b][g * CAP];

        float m = -1e30f, ssum = 0.f, zx = 0.f, zy = 0.f;
        for (int t0 = 0; t0 < cnt; t0 += 8) {
            float2 xr[8];
            float  p[8];
            #pragma unroll
            for (int j = 0; j < 8; j++) {
                int t = t0 + j;
                int src = (t < cnt) ? srcs[t] : self;   // dummy rows get pw forced 0
                xr[j] = *(const float2*)(xp + (size_t)src * SS + 2 * lane);
                p[j] = xr[j].x * ws.x + xr[j].y * ws.y;
            }
            #pragma unroll
            for (int o = 16; o; o >>= 1) {
                #pragma unroll
                for (int j = 0; j < 8; j++) p[j] += __shfl_xor_sync(FULL, p[j], o);
            }
            float e[8], cm = -1e30f;
            #pragma unroll
            for (int j = 0; j < 8; j++) {
                float v = p[j] + a_dst;
                v = (v > 0.f) ? v : NEG * v;            // leaky_relu
                if (t0 + j >= cnt) v = -1e30f;
                e[j] = v;
                cm = fmaxf(cm, v);
            }
            float mn = fmaxf(m, cm);
            float sc = __expf(m - mn);
            ssum *= sc; zx *= sc; zy *= sc;
            #pragma unroll
            for (int j = 0; j < 8; j++) {
                float pw = __expf(e[j] - mn);
                ssum += pw;
                zx += pw * xr[j].x;
                zy += pw * xr[j].y;
            }
            m = mn;
        }
        const float inv = 1.f / (ssum + 1e-16f);
        zx *= inv; zy *= inv;

        // matvec: res = sigmoid(z @ W + bias)
        float a0 = 0.f, a1 = 0.f, a2 = 0.f, a3 = 0.f;
        #pragma unroll 8
        for (int k2 = 0; k2 < 32; k2++) {
            float z0 = __shfl_sync(FULL, zx, k2);
            float z1 = __shfl_sync(FULL, zy, k2);
            float4 wA = *(const float4*)(Wb + (2 * k2) * HH + l4);
            float4 wB = *(const float4*)(Wb + (2 * k2 + 1) * HH + l4);
            a0 += z0 * wA.x + z1 * wB.x;
            a1 += z0 * wA.y + z1 * wB.y;
            a2 += z0 * wA.z + z1 * wB.z;
            a3 += z0 * wA.w + z1 * wB.w;
        }
        const float* Bb = shB + b * HH;
        float4 sg;
        sg.x = 1.f / (1.f + __expf(-(a0 + Bb[l4])));
        sg.y = 1.f / (1.f + __expf(-(a1 + Bb[l4 + 1])));
        sg.z = 1.f / (1.f + __expf(-(a2 + Bb[l4 + 2])));
        sg.w = 1.f / (1.f + __expf(-(a3 + Bb[l4 + 3])));
        *(float4*)&shRes[(gl * 2 + b) * HH + l4] = sg;
    }
    __syncthreads();

    // combine: warp w handles graph gbase + w
    {
        float4 u  = *(const float4*)&shRes[(w * 2 + 0) * HH + l4];
        float4 d  = *(const float4*)&shRes[(w * 2 + 1) * HH + l4];
        float4 mw = *(const float4*)&shMlp[l4];
        float p = u.x * d.x * mw.x + u.y * d.y * mw.y +
                  u.z * d.z * mw.z + u.w * d.w * mw.w;
        #pragma unroll
        for (int o = 16; o; o >>= 1) p += __shfl_xor_sync(FULL, p, o);
        if (lane == 0) out[gbase + w] = p + mlp_b[0];
    }
}

extern "C" void kernel_launch(void* const* d_in, const int* in_sizes, int n_in,
                              void* d_out, int out_size) {
    const float* up_x    = (const float*)d_in[0];
    const void*  up_e    = d_in[1];
    const float* down_x  = (const float*)d_in[3];
    const void*  down_e  = d_in[4];
    const float* up_W    = (const float*)d_in[6];
    const float* up_as   = (const float*)d_in[7];
    const float* up_ad   = (const float*)d_in[8];
    const float* up_b    = (const float*)d_in[9];
    const float* down_W  = (const float*)d_in[10];
    const float* down_as = (const float*)d_in[11];
    const float* down_ad = (const float*)d_in[12];
    const float* down_b  = (const float*)d_in[13];
    const float* mlp_W   = (const float*)d_in[14];
    const float* mlp_b   = (const float*)d_in[15];
    float* out = (float*)d_out;

    cudaFuncSetAttribute(fused_tail_kernel,
                         cudaFuncAttributeMaxDynamicSharedMemorySize, SMB);

    pre_kernel<<<34, 256>>>((const int*)up_e, up_W, up_as, up_ad,
                            down_W, down_as, down_ad);
    filter_edges_kernel<<<2 * (EE / 8) / 256, 256>>>(up_e, down_e);
    fused_tail_kernel<<<GG / TGPB, 256, SMB>>>(up_x, down_x,
                                               up_W, up_b, down_W, down_b,
                                               mlp_W, mlp_b, out);
}